// round 5
// baseline (speedup 1.0000x reference)
#include <cuda_runtime.h>
#include <cstdint>

// ---------------- problem constants ----------------
#define B_ROWS 1024
#define DIM    192
#define NCLS   100000

#define TN  128          // classes per CTA tile
#define RB  128          // rows per inner block
#define NRB (B_ROWS/RB)  // 8
#define KB  (DIM/8)      // 24 k8-steps
#define STR 196          // smem row stride (words), 196%32==4 -> conflict-free frags

#define S_SCALE 30.0f
#define LOG2E_F 1.4426950408889634f
#define SLOG2E  (S_SCALE * LOG2E_F)
#define COS_M_C 0.98006657784124163f
#define SIN_M_C 0.19866933079506122f
#define TH_C    (-0.98006657784124163f)
#define MM_C    0.039733866159012244f

// ---------------- scratch (device globals; no allocation) ----------------
__device__ double             g_rowsum[B_ROWS];
__device__ unsigned long long g_rowmax[B_ROWS];
__device__ float              g_label_t[B_ROWS];   // adjusted label logit (log2-scaled)
__device__ float              g_xn[B_ROWS * DIM];  // normalized x, tf32-rounded
__device__ int                g_lab64;             // 1 if labels are int64, else int32

// ---------------- helpers ----------------
__device__ __forceinline__ float to_tf32(float x) {
    uint32_t u;
    asm("cvt.rna.tf32.f32 %0, %1;" : "=r"(u) : "f"(x));
    return __uint_as_float(u);
}

__device__ __forceinline__ unsigned int fkey(float v) {
    unsigned int u = __float_as_uint(v);
    return (u & 0x80000000u) ? ~u : (u | 0x80000000u);
}

__device__ __forceinline__ void mma_tf32(float* d, const uint32_t* a, const uint32_t* b) {
    asm volatile(
        "mma.sync.aligned.m16n8k8.row.col.f32.tf32.tf32.f32 "
        "{%0,%1,%2,%3}, {%4,%5,%6,%7}, {%8,%9}, {%0,%1,%2,%3};"
        : "+f"(d[0]), "+f"(d[1]), "+f"(d[2]), "+f"(d[3])
        : "r"(a[0]), "r"(a[1]), "r"(a[2]), "r"(a[3]), "r"(b[0]), "r"(b[1]));
}

__device__ __forceinline__ int load_label(const void* lp, int i, int is64) {
    if (is64) return (int)(((const long long*)lp)[i]);
    return ((const int*)lp)[i];
}

// ---------------- kernel 0a: detect label dtype ----------------
// int64 labels (values < 2^31) have every odd 32-bit word == 0.
// For int32 labels the odd words are labels themselves (all-zero prob ~0).
// Reads only the first 4KB -> in-bounds for both dtypes.
__global__ void detect_kernel(const int* __restrict__ lw) {
    __shared__ int any;
    if (threadIdx.x == 0) any = 0;
    __syncthreads();
    int i = threadIdx.x;  // 512 threads check words 1,3,...,1023
    if (i < 512 && lw[2 * i + 1] != 0) atomicOr(&any, 1);
    __syncthreads();
    if (threadIdx.x == 0) g_lab64 = (any == 0) ? 1 : 0;
}

// ---------------- kernel 0b: normalize x (tf32), zero per-row scratch ----------------
__global__ void prep_kernel(const float* __restrict__ x) {
    int b = blockIdx.x;
    int k = threadIdx.x;  // DIM = 192 threads = 6 warps
    float v = x[b * DIM + k];
    float ss = v * v;
    #pragma unroll
    for (int o = 16; o > 0; o >>= 1) ss += __shfl_xor_sync(0xffffffffu, ss, o);
    __shared__ float wp[6];
    __shared__ float inv_s;
    int w = k >> 5, l = k & 31;
    if (l == 0) wp[w] = ss;
    __syncthreads();
    if (k == 0) {
        float t = 0.f;
        #pragma unroll
        for (int i = 0; i < 6; i++) t += wp[i];
        float n = sqrtf(t);
        inv_s = 1.0f / fmaxf(n, 1e-12f);
        g_rowsum[b] = 0.0;
        g_rowmax[b] = 0ull;
    }
    __syncthreads();
    g_xn[b * DIM + k] = to_tf32(v * inv_s);
}

// ---------------- kernel 1: fused GEMM + margin + softmax-partials ----------------
extern __shared__ float smem_f[];

__global__ __launch_bounds__(256, 1) void gemm_epi_kernel(const float* __restrict__ wgt,
                                                          const void* __restrict__ label) {
    float* ws  = smem_f;             // TN * STR
    float* xs  = ws + TN * STR;      // RB * STR
    float* a_s = xs + RB * STR;      // TN : per-class scale S*log2e/||w_c||
    int*   lbl = (int*)(a_s + TN);   // B_ROWS

    const int tid = threadIdx.x;
    const int c0  = blockIdx.x * TN;
    const int is64 = g_lab64;

    for (int i = tid; i < B_ROWS; i += 256) lbl[i] = load_label(label, i, is64);

    // load W tile, rounding to tf32
    for (int i = tid; i < TN * (DIM / 4); i += 256) {
        int c = i / (DIM / 4), j = i % (DIM / 4);
        int cg = c0 + c;
        float4 v = make_float4(0.f, 0.f, 0.f, 0.f);
        if (cg < NCLS) v = reinterpret_cast<const float4*>(wgt)[cg * (DIM / 4) + j];
        float* p = ws + c * STR + 4 * j;
        p[0] = to_tf32(v.x); p[1] = to_tf32(v.y); p[2] = to_tf32(v.z); p[3] = to_tf32(v.w);
    }
    __syncthreads();

    // per-class combined scale
    if (tid < TN) {
        float ss = 0.f;
        const float* p = ws + tid * STR;
        #pragma unroll 8
        for (int k = 0; k < DIM; k++) { float v = p[k]; ss += v * v; }
        a_s[tid] = (ss > 0.f) ? SLOG2E * rsqrtf(ss) : 0.f;
    }

    const int lane = tid & 31;
    const int g = lane >> 2, tig = lane & 3;
    const int warp = tid >> 5;
    const int wm = warp >> 1, wn = warp & 1;  // 4x2 warp grid: 32 rows x 64 cols each

    for (int rb = 0; rb < NRB; rb++) {
        __syncthreads();  // also covers a_s writes before first epilogue read
        for (int i = tid; i < RB * (DIM / 4); i += 256) {
            int r = i / (DIM / 4), j = i % (DIM / 4);
            float4 v = reinterpret_cast<const float4*>(g_xn)[(rb * RB + r) * (DIM / 4) + j];
            *reinterpret_cast<float4*>(xs + r * STR + 4 * j) = v;
        }
        __syncthreads();

        float acc[2][8][4];
        #pragma unroll
        for (int mi = 0; mi < 2; mi++)
            #pragma unroll
            for (int ni = 0; ni < 8; ni++)
                #pragma unroll
                for (int q = 0; q < 4; q++) acc[mi][ni][q] = 0.f;

        #pragma unroll
        for (int kb = 0; kb < KB; kb++) {
            const int k = kb * 8;
            uint32_t af[2][4];
            #pragma unroll
            for (int mi = 0; mi < 2; mi++) {
                int r0 = wm * 32 + mi * 16 + g;
                af[mi][0] = __float_as_uint(xs[r0 * STR + k + tig]);
                af[mi][1] = __float_as_uint(xs[(r0 + 8) * STR + k + tig]);
                af[mi][2] = __float_as_uint(xs[r0 * STR + k + tig + 4]);
                af[mi][3] = __float_as_uint(xs[(r0 + 8) * STR + k + tig + 4]);
            }
            uint32_t bf[8][2];
            #pragma unroll
            for (int ni = 0; ni < 8; ni++) {
                int cc = wn * 64 + ni * 8 + g;
                bf[ni][0] = __float_as_uint(ws[cc * STR + k + tig]);
                bf[ni][1] = __float_as_uint(ws[cc * STR + k + tig + 4]);
            }
            #pragma unroll
            for (int mi = 0; mi < 2; mi++)
                #pragma unroll
                for (int ni = 0; ni < 8; ni++)
                    mma_tf32(acc[mi][ni], af[mi], bf[ni]);
        }

        // fused epilogue: margin at label col, exp2 sum, argmax
        #pragma unroll
        for (int mi = 0; mi < 2; mi++) {
            #pragma unroll
            for (int half = 0; half < 2; half++) {
                int row = rb * RB + wm * 32 + mi * 16 + g + half * 8;
                int lab = lbl[row];
                float psum = 0.f, tmax = -1e30f;
                int cmax = 0;
                #pragma unroll
                for (int ni = 0; ni < 8; ni++) {
                    #pragma unroll
                    for (int q = 0; q < 2; q++) {
                        int c = c0 + wn * 64 + ni * 8 + tig * 2 + q;
                        if (c < NCLS) {
                            float d = acc[mi][ni][half * 2 + q];
                            float t = d * a_s[c - c0];  // = S*log2e*cosine
                            if (c == lab) {
                                float cs = t * (1.0f / SLOG2E);
                                float s2 = fmaxf(1.0f - cs * cs, 0.f);
                                float sn = sqrtf(s2);
                                float ph = cs * COS_M_C - sn * SIN_M_C;
                                if (!(cs - TH_C > 0.f)) ph = cs - MM_C;
                                t = ph * SLOG2E;
                                g_label_t[row] = t;  // single writer per row
                            }
                            psum += exp2f(t);
                            if (t > tmax) { tmax = t; cmax = c; }
                        }
                    }
                }
                psum += __shfl_xor_sync(0xffffffffu, psum, 1);
                psum += __shfl_xor_sync(0xffffffffu, psum, 2);
                unsigned long long key =
                    ((unsigned long long)fkey(tmax) << 32) |
                    (unsigned long long)(0xFFFFFFFFu - (unsigned)cmax);
                unsigned long long o;
                o = __shfl_xor_sync(0xffffffffu, key, 1); key = key > o ? key : o;
                o = __shfl_xor_sync(0xffffffffu, key, 2); key = key > o ? key : o;
                if (tig == 0) {
                    atomicAdd(&g_rowsum[row], (double)psum);
                    atomicMax(&g_rowmax[row], key);
                }
            }
        }
    }
}

// ---------------- kernel 2: finalize loss + prec1 ----------------
__global__ void finalize_kernel(const void* __restrict__ label, float* __restrict__ out,
                                int out_n) {
    __shared__ float sl[B_ROWS];
    __shared__ int   sh[B_ROWS];
    int b = threadIdx.x;
    double s = g_rowsum[b];
    double lse2 = log2(s);  // lse_nat = ln2 * log2(sum)
    float loss_b = (float)((lse2 - (double)g_label_t[b]) * 0.6931471805599453);
    unsigned int idx = 0xFFFFFFFFu - (unsigned int)(g_rowmax[b] & 0xFFFFFFFFull);
    int lab = load_label(label, b, g_lab64);
    sl[b] = loss_b;
    sh[b] = (idx == (unsigned int)lab) ? 1 : 0;
    __syncthreads();
    for (int st = B_ROWS / 2; st > 0; st >>= 1) {
        if (b < st) { sl[b] += sl[b + st]; sh[b] += sh[b + st]; }
        __syncthreads();
    }
    if (b == 0) {
        out[0] = sl[0] * (1.0f / B_ROWS);
        if (out_n > 1) out[1] = (float)sh[0] * (100.0f / B_ROWS);
    }
}

// ---------------- launch ----------------
extern "C" void kernel_launch(void* const* d_in, const int* in_sizes, int n_in,
                              void* d_out, int out_size) {
    const float* x   = (const float*)d_in[0];
    const float* wgt = (const float*)d_in[1];
    const void*  lab = d_in[2];
    float* out = (float*)d_out;
    (void)in_sizes; (void)n_in;

    const size_t shbytes = (size_t)(TN * STR + RB * STR + TN) * 4 + (size_t)B_ROWS * 4;
    cudaFuncSetAttribute(gemm_epi_kernel, cudaFuncAttributeMaxDynamicSharedMemorySize,
                         (int)shbytes);

    detect_kernel<<<1, 1024>>>((const int*)lab);
    prep_kernel<<<B_ROWS, DIM>>>(x);
    int ntiles = (NCLS + TN - 1) / TN;  // 782
    gemm_epi_kernel<<<ntiles, 256, shbytes>>>(wgt, lab);
    finalize_kernel<<<1, B_ROWS>>>(lab, out, out_size);
}

// round 8
// speedup vs baseline: 1.4286x; 1.4286x over previous
#include <cuda_runtime.h>
#include <cuda_bf16.h>
#include <cstdint>

// ---------------- problem constants ----------------
#define B_ROWS 1024
#define DIM    192
#define NCLS   100000

#define TN  128                        // classes per CTA tile
#define RB  128                        // rows per inner block
#define NRB (B_ROWS / RB)              // 8
#define NT  ((NCLS + TN - 1) / TN)     // 782 tiles
#define NKB (DIM / 16)                 // 12 k16-steps
#define STR 200                        // smem row stride in bf16 elems (400B: 16B-aligned, %128B=16 -> conflict-free LDSM)
#define STRB (STR * 2)                 // 400 bytes

#define S_SCALE 30.0f
#define LOG2E_F 1.4426950408889634f
#define SLOG2E  (S_SCALE * LOG2E_F)
#define COS_M_C 0.98006657784124163f
#define SIN_M_C 0.19866933079506122f
#define TH_C    (-0.98006657784124163f)
#define MM_C    0.039733866159012244f

// ---------------- smem layout (bytes) ----------------
#define WS_OFF   0                       // W tile: 128 rows x 400B
#define WS_SZ    (TN * STRB)             // 51200
#define XS0_OFF  (WS_OFF + WS_SZ)
#define XS_SZ    (RB * STRB)             // 51200
#define XS1_OFF  (XS0_OFF + XS_SZ)
#define AS_OFF   (XS1_OFF + XS_SZ)       // 128 floats
#define LBL_OFF  (AS_OFF + TN * 4)       // 1024 ints
#define SMEM_TOTAL (LBL_OFF + B_ROWS * 4)  // 158208

// ---------------- scratch (device globals; no allocation) ----------------
__device__ double             g_rowsum[B_ROWS];
__device__ unsigned long long g_rowmax[B_ROWS];
__device__ float              g_label_t[B_ROWS];
__device__ __nv_bfloat16      g_xbf[B_ROWS * DIM];        // normalized x, bf16
__device__ __nv_bfloat16      g_wbf[(size_t)NCLS * DIM];  // w rounded to bf16
__device__ float              g_ascale[NCLS];             // S*log2e / ||w_bf16||
__device__ int                g_lab64;

// ---------------- helpers ----------------
__device__ __forceinline__ uint32_t smem_u32(const void* p) {
    uint32_t a;
    asm("{ .reg .u64 t; cvta.to.shared.u64 t, %1; cvt.u32.u64 %0, t; }" : "=r"(a) : "l"(p));
    return a;
}
#define CP_ASYNC16(dst, src) \
    asm volatile("cp.async.cg.shared.global [%0], [%1], 16;" :: "r"(dst), "l"(src) : "memory")
#define CP_COMMIT() asm volatile("cp.async.commit_group;" ::: "memory")
#define CP_WAIT0()  asm volatile("cp.async.wait_group 0;" ::: "memory")

#define LDSM4(r0, r1, r2, r3, a) \
    asm volatile("ldmatrix.sync.aligned.m8n8.x4.shared.b16 {%0,%1,%2,%3}, [%4];" \
                 : "=r"(r0), "=r"(r1), "=r"(r2), "=r"(r3) : "r"(a))

__device__ __forceinline__ void mma_bf16(float* d, const uint32_t* a, const uint32_t* b) {
    asm volatile(
        "mma.sync.aligned.m16n8k16.row.col.f32.bf16.bf16.f32 "
        "{%0,%1,%2,%3}, {%4,%5,%6,%7}, {%8,%9}, {%0,%1,%2,%3};"
        : "+f"(d[0]), "+f"(d[1]), "+f"(d[2]), "+f"(d[3])
        : "r"(a[0]), "r"(a[1]), "r"(a[2]), "r"(a[3]), "r"(b[0]), "r"(b[1]));
}
__device__ __forceinline__ unsigned int fkey(float v) {
    unsigned int u = __float_as_uint(v);
    return (u & 0x80000000u) ? ~u : (u | 0x80000000u);
}
__device__ __forceinline__ int load_label(const void* lp, int i, int is64) {
    if (is64) return (int)(((const long long*)lp)[i]);
    return ((const int*)lp)[i];
}

// ---------------- kernel 0a: detect label dtype ----------------
__global__ void detect_kernel(const int* __restrict__ lw) {
    __shared__ int any;
    if (threadIdx.x == 0) any = 0;
    __syncthreads();
    int i = threadIdx.x;
    if (i < 512 && lw[2 * i + 1] != 0) atomicOr(&any, 1);
    __syncthreads();
    if (threadIdx.x == 0) g_lab64 = (any == 0) ? 1 : 0;
}

// ---------------- kernel 0b: normalize x -> bf16, zero row scratch ----------------
__global__ void prep_x_kernel(const float* __restrict__ x) {
    int b = blockIdx.x, k = threadIdx.x;  // 192 threads
    float v = x[b * DIM + k];
    float ss = v * v;
    #pragma unroll
    for (int o = 16; o > 0; o >>= 1) ss += __shfl_xor_sync(0xffffffffu, ss, o);
    __shared__ float wp[6];
    __shared__ float inv_s;
    if ((k & 31) == 0) wp[k >> 5] = ss;
    __syncthreads();
    if (k == 0) {
        float t = 0.f;
        #pragma unroll
        for (int i = 0; i < 6; i++) t += wp[i];
        inv_s = 1.0f / fmaxf(sqrtf(t), 1e-12f);
        g_rowsum[b] = 0.0;
        g_rowmax[b] = 0ull;
    }
    __syncthreads();
    g_xbf[b * DIM + k] = __float2bfloat16(v * inv_s);
}

// ---------------- kernel 0c: w -> bf16 + per-class combined scale ----------------
__global__ void prep_w_kernel(const float* __restrict__ wgt) {
    int c = blockIdx.x * 4 + (threadIdx.x >> 5);  // 1 class per warp
    int l = threadIdx.x & 31;
    if (c >= NCLS) return;
    const float* wr = wgt + (size_t)c * DIM;
    __nv_bfloat16* wo = g_wbf + (size_t)c * DIM;
    float ss = 0.f;
    #pragma unroll
    for (int i = 0; i < 6; i++) {
        float v = wr[l * 6 + i];
        __nv_bfloat16 bv = __float2bfloat16(v);
        float vb = __bfloat162float(bv);
        ss += vb * vb;
        wo[l * 6 + i] = bv;
    }
    #pragma unroll
    for (int o = 16; o > 0; o >>= 1) ss += __shfl_xor_sync(0xffffffffu, ss, o);
    if (l == 0) g_ascale[c] = (ss > 0.f) ? SLOG2E * rsqrtf(ss) : 0.f;
}

// ---------------- kernel 1: bf16 HMMA GEMM + fused margin/softmax epilogue --------
__global__ void __launch_bounds__(256, 1)
gemm_epi_kernel(const void* __restrict__ label) {
    extern __shared__ char smem[];
    const uint32_t sb = smem_u32(smem);
    const int tid = threadIdx.x;
    const int warp = tid >> 5, lane = tid & 31;
    const int c0 = blockIdx.x * TN;

    float* a_sp = (float*)(smem + AS_OFF);
    int*   lblp = (int*)(smem + LBL_OFF);

    // labels + per-class scales
    const int is64 = g_lab64;
    for (int i = tid; i < B_ROWS; i += 256) lblp[i] = load_label(label, i, is64);
    if (tid < TN) {
        int cg = c0 + tid;
        a_sp[tid] = g_ascale[(cg < NCLS) ? cg : (NCLS - 1)];
    }

    // W tile + X block 0 via cp.async (24 x 16B chunks per 192-elem row)
    for (int i = tid; i < TN * 24; i += 256) {
        int c = i / 24, j = i % 24;
        int cg = c0 + c; if (cg >= NCLS) cg = NCLS - 1;  // clamp; epilogue guards
        CP_ASYNC16(sb + WS_OFF + c * STRB + j * 16,
                   (const char*)g_wbf + (size_t)cg * (DIM * 2) + j * 16);
    }
    for (int i = tid; i < RB * 24; i += 256) {
        int r = i / 24, j = i % 24;
        CP_ASYNC16(sb + XS0_OFF + r * STRB + j * 16,
                   (const char*)g_xbf + (size_t)r * (DIM * 2) + j * 16);
    }
    CP_COMMIT();
    CP_WAIT0();
    __syncthreads();

    // warp grid: 4 (rows) x 2 (cols); each warp: 32 rows x 64 cols
    const int wm = warp >> 1, wn = warp & 1;
    const int g = lane >> 2, tig = lane & 3;

    // ldmatrix lane address components
    // A: mat = lane>>3 -> row_add=(mat&1)*8, k_add=(mat>>1)*8
    const int a_row = wm * 32 + (lane & 7) + ((lane >> 3) & 1) * 8;
    const uint32_t a_koff = ((lane >> 4) & 1) * 16;  // bytes
    // B: mat -> ntile_add=(mat>>1), k_add=(mat&1)*8
    const int b_mat = lane >> 3;
    const int b_row = wn * 64 + (b_mat >> 1) * 8 + (lane & 7);
    const uint32_t b_koff = (b_mat & 1) * 16;  // bytes
    uint32_t b_addr[4];
    #pragma unroll
    for (int p = 0; p < 4; p++)
        b_addr[p] = sb + WS_OFF + (b_row + p * 16) * STRB + b_koff;

    // per-lane class scales (constant across row blocks)
    float asv[8][2];
    #pragma unroll
    for (int ni = 0; ni < 8; ni++)
        #pragma unroll
        for (int q = 0; q < 2; q++)
            asv[ni][q] = a_sp[wn * 64 + ni * 8 + tig * 2 + q];

    for (int blk = 0; blk < NRB; blk++) {
        const uint32_t xbase = sb + ((blk & 1) ? XS1_OFF : XS0_OFF);
        if (blk + 1 < NRB) {  // prefetch next X block under compute
            uint32_t xb = sb + (((blk + 1) & 1) ? XS1_OFF : XS0_OFF);
            for (int i = tid; i < RB * 24; i += 256) {
                int r = i / 24, j = i % 24;
                CP_ASYNC16(xb + r * STRB + j * 16,
                           (const char*)g_xbf + ((size_t)(blk + 1) * RB + r) * (DIM * 2) + j * 16);
            }
            CP_COMMIT();
        }

        float acc[2][8][4];
        #pragma unroll
        for (int mi = 0; mi < 2; mi++)
            #pragma unroll
            for (int ni = 0; ni < 8; ni++)
                #pragma unroll
                for (int q = 0; q < 4; q++) acc[mi][ni][q] = 0.f;

        const uint32_t xa0 = xbase + a_row * STRB + a_koff;
        const uint32_t xa1 = xa0 + 16 * STRB;

        #pragma unroll
        for (int kb = 0; kb < NKB; kb++) {
            const uint32_t kadd = kb * 32;  // 16 bf16 = 32 bytes
            uint32_t af[2][4];
            LDSM4(af[0][0], af[0][1], af[0][2], af[0][3], xa0 + kadd);
            LDSM4(af[1][0], af[1][1], af[1][2], af[1][3], xa1 + kadd);
            uint32_t bf[8][2];
            #pragma unroll
            for (int p = 0; p < 4; p++)
                LDSM4(bf[2 * p][0], bf[2 * p][1], bf[2 * p + 1][0], bf[2 * p + 1][1],
                      b_addr[p] + kadd);
            #pragma unroll
            for (int mi = 0; mi < 2; mi++)
                #pragma unroll
                for (int ni = 0; ni < 8; ni++)
                    mma_bf16(acc[mi][ni], af[mi], bf[ni]);
        }

        // fused epilogue: margin at label col, exp2 partial sum, argmax
        #pragma unroll
        for (int mi = 0; mi < 2; mi++) {
            #pragma unroll
            for (int half = 0; half < 2; half++) {
                int row = blk * RB + wm * 32 + mi * 16 + g + half * 8;
                int lab = lblp[row];
                float psum = 0.f, tmax = -1e30f;
                int cmax = 0;
                #pragma unroll
                for (int ni = 0; ni < 8; ni++) {
                    #pragma unroll
                    for (int q = 0; q < 2; q++) {
                        int c = c0 + wn * 64 + ni * 8 + tig * 2 + q;
                        if (c < NCLS) {
                            float t = acc[mi][ni][half * 2 + q] * asv[ni][q];
                            if (c == lab) {
                                float cs = t * (1.0f / SLOG2E);
                                float sn = sqrtf(fmaxf(1.0f - cs * cs, 0.f));
                                float ph = cs * COS_M_C - sn * SIN_M_C;
                                if (!(cs - TH_C > 0.f)) ph = cs - MM_C;
                                t = ph * SLOG2E;
                                g_label_t[row] = t;  // unique writer per row
                            }
                            psum += exp2f(t);
                            if (t > tmax) { tmax = t; cmax = c; }
                        }
                    }
                }
                psum += __shfl_xor_sync(0xffffffffu, psum, 1);
                psum += __shfl_xor_sync(0xffffffffu, psum, 2);
                unsigned long long key =
                    ((unsigned long long)fkey(tmax) << 32) |
                    (unsigned long long)(0xFFFFFFFFu - (unsigned)cmax);
                unsigned long long o;
                o = __shfl_xor_sync(0xffffffffu, key, 1); key = key > o ? key : o;
                o = __shfl_xor_sync(0xffffffffu, key, 2); key = key > o ? key : o;
                if (tig == 0) {
                    atomicAdd(&g_rowsum[row], (double)psum);
                    atomicMax(&g_rowmax[row], key);
                }
            }
        }

        if (blk + 1 < NRB) {
            CP_WAIT0();
            __syncthreads();
        }
    }
}

// ---------------- kernel 2: finalize loss + prec1 ----------------
__global__ void finalize_kernel(const void* __restrict__ label, float* __restrict__ out,
                                int out_n) {
    __shared__ float sl[B_ROWS];
    __shared__ int   sh[B_ROWS];
    int b = threadIdx.x;
    float s = (float)g_rowsum[b];
    float loss_b = (log2f(s) - g_label_t[b]) * 0.6931471805599453f;
    unsigned int idx = 0xFFFFFFFFu - (unsigned int)(g_rowmax[b] & 0xFFFFFFFFull);
    int lab = load_label(label, b, g_lab64);
    sl[b] = loss_b;
    sh[b] = (idx == (unsigned int)lab) ? 1 : 0;
    __syncthreads();
    for (int st = B_ROWS / 2; st > 0; st >>= 1) {
        if (b < st) { sl[b] += sl[b + st]; sh[b] += sh[b + st]; }
        __syncthreads();
    }
    if (b == 0) {
        out[0] = sl[0] * (1.0f / B_ROWS);
        if (out_n > 1) out[1] = (float)sh[0] * (100.0f / B_ROWS);
    }
}

// ---------------- launch ----------------
extern "C" void kernel_launch(void* const* d_in, const int* in_sizes, int n_in,
                              void* d_out, int out_size) {
    const float* x   = (const float*)d_in[0];
    const float* wgt = (const float*)d_in[1];
    const void*  lab = d_in[2];
    float* out = (float*)d_out;
    (void)in_sizes; (void)n_in;

    cudaFuncSetAttribute(gemm_epi_kernel, cudaFuncAttributeMaxDynamicSharedMemorySize,
                         SMEM_TOTAL);

    detect_kernel<<<1, 1024>>>((const int*)lab);
    prep_x_kernel<<<B_ROWS, DIM>>>(x);
    prep_w_kernel<<<(NCLS + 3) / 4, 128>>>(wgt);
    gemm_epi_kernel<<<NT, 256, SMEM_TOTAL>>>(lab);
    finalize_kernel<<<1, B_ROWS>>>(lab, out, out_size);
}

// round 9
// speedup vs baseline: 1.9134x; 1.3394x over previous
#include <cuda_runtime.h>
#include <cuda_bf16.h>
#include <cstdint>

// ---------------- problem constants ----------------
#define B_ROWS 1024
#define DIM    192
#define NCLS   100000

#define TN  128                        // classes per CTA tile
#define RB  64                         // rows per inner block (halved for occupancy)
#define NRB (B_ROWS / RB)              // 16
#define NT  ((NCLS + TN - 1) / TN)     // 782 tiles
#define NKB (DIM / 16)                 // 12 k16-steps
#define STR 200                        // smem row stride in bf16 elems (400B)
#define STRB (STR * 2)                 // 400 bytes

#define S_SCALE 30.0f
#define LOG2E_F 1.4426950408889634f
#define SLOG2E  (S_SCALE * LOG2E_F)
#define COS_M_C 0.98006657784124163f
#define SIN_M_C 0.19866933079506122f
#define TH_C    (-0.98006657784124163f)
#define MM_C    0.039733866159012244f

// ---------------- smem layout (bytes) ----------------
#define WS_OFF   0                       // W tile: 128 rows x 400B
#define WS_SZ    (TN * STRB)             // 51200
#define XS0_OFF  (WS_OFF + WS_SZ)
#define XS_SZ    (RB * STRB)             // 25600
#define XS1_OFF  (XS0_OFF + XS_SZ)
#define AS_OFF   (XS1_OFF + XS_SZ)       // 128 floats
#define LBL_OFF  (AS_OFF + TN * 4)
#define SMEM_TOTAL (LBL_OFF + B_ROWS * 4)  // 107008 -> 2 CTAs/SM

// ---------------- scratch (device globals; no allocation) ----------------
__device__ float              g_rowsum[B_ROWS];
__device__ unsigned long long g_rowmax[B_ROWS];
__device__ float              g_label_t[B_ROWS];
__device__ __nv_bfloat16      g_xbf[B_ROWS * DIM];        // normalized x, bf16
__device__ __nv_bfloat16      g_wbf[(size_t)NCLS * DIM];  // w rounded to bf16
__device__ float              g_ascale[NCLS];             // S*log2e / ||w_bf16||
__device__ int                g_lab64;

// ---------------- helpers ----------------
__device__ __forceinline__ uint32_t smem_u32(const void* p) {
    uint32_t a;
    asm("{ .reg .u64 t; cvta.to.shared.u64 t, %1; cvt.u32.u64 %0, t; }" : "=r"(a) : "l"(p));
    return a;
}
#define CP_ASYNC16(dst, src) \
    asm volatile("cp.async.cg.shared.global [%0], [%1], 16;" :: "r"(dst), "l"(src) : "memory")
#define CP_COMMIT() asm volatile("cp.async.commit_group;" ::: "memory")
#define CP_WAIT0()  asm volatile("cp.async.wait_group 0;" ::: "memory")

#define LDSM4(r0, r1, r2, r3, a) \
    asm volatile("ldmatrix.sync.aligned.m8n8.x4.shared.b16 {%0,%1,%2,%3}, [%4];" \
                 : "=r"(r0), "=r"(r1), "=r"(r2), "=r"(r3) : "r"(a))

__device__ __forceinline__ void mma_bf16(float* d, const uint32_t* a, const uint32_t* b) {
    asm volatile(
        "mma.sync.aligned.m16n8k16.row.col.f32.bf16.bf16.f32 "
        "{%0,%1,%2,%3}, {%4,%5,%6,%7}, {%8,%9}, {%0,%1,%2,%3};"
        : "+f"(d[0]), "+f"(d[1]), "+f"(d[2]), "+f"(d[3])
        : "r"(a[0]), "r"(a[1]), "r"(a[2]), "r"(a[3]), "r"(b[0]), "r"(b[1]));
}
__device__ __forceinline__ unsigned int fkey(float v) {
    unsigned int u = __float_as_uint(v);
    return (u & 0x80000000u) ? ~u : (u | 0x80000000u);
}
__device__ __forceinline__ int load_label(const void* lp, int i, int is64) {
    if (is64) return (int)(((const long long*)lp)[i]);
    return ((const int*)lp)[i];
}

// ---------------- kernel 0a: detect label dtype ----------------
__global__ void detect_kernel(const int* __restrict__ lw) {
    __shared__ int any;
    if (threadIdx.x == 0) any = 0;
    __syncthreads();
    int i = threadIdx.x;
    if (i < 512 && lw[2 * i + 1] != 0) atomicOr(&any, 1);
    __syncthreads();
    if (threadIdx.x == 0) g_lab64 = (any == 0) ? 1 : 0;
}

// ---------------- kernel 0b: normalize x -> bf16, zero row scratch ----------------
__global__ void prep_x_kernel(const float* __restrict__ x) {
    int b = blockIdx.x, k = threadIdx.x;  // 192 threads
    float v = x[b * DIM + k];
    float ss = v * v;
    #pragma unroll
    for (int o = 16; o > 0; o >>= 1) ss += __shfl_xor_sync(0xffffffffu, ss, o);
    __shared__ float wp[6];
    __shared__ float inv_s;
    if ((k & 31) == 0) wp[k >> 5] = ss;
    __syncthreads();
    if (k == 0) {
        float t = 0.f;
        #pragma unroll
        for (int i = 0; i < 6; i++) t += wp[i];
        inv_s = 1.0f / fmaxf(sqrtf(t), 1e-12f);
        g_rowsum[b] = 0.f;
        g_rowmax[b] = 0ull;
    }
    __syncthreads();
    g_xbf[b * DIM + k] = __float2bfloat16(v * inv_s);
}

// ---------------- kernel 0c: w -> bf16 + per-class combined scale ----------------
__global__ void prep_w_kernel(const float* __restrict__ wgt) {
    int c = blockIdx.x * 4 + (threadIdx.x >> 5);  // 1 class per warp
    int l = threadIdx.x & 31;
    if (c >= NCLS) return;
    const float* wr = wgt + (size_t)c * DIM;
    __nv_bfloat16* wo = g_wbf + (size_t)c * DIM;
    float ss = 0.f;
    #pragma unroll
    for (int i = 0; i < 6; i++) {
        float v = wr[l * 6 + i];
        __nv_bfloat16 bv = __float2bfloat16(v);
        float vb = __bfloat162float(bv);
        ss += vb * vb;
        wo[l * 6 + i] = bv;
    }
    #pragma unroll
    for (int o = 16; o > 0; o >>= 1) ss += __shfl_xor_sync(0xffffffffu, ss, o);
    if (l == 0) g_ascale[c] = (ss > 0.f) ? SLOG2E * rsqrtf(ss) : 0.f;
}

// ---------------- kernel 1: bf16 HMMA GEMM + fused margin/softmax epilogue --------
__global__ void __launch_bounds__(256, 2)
gemm_epi_kernel(const void* __restrict__ label) {
    extern __shared__ char smem[];
    const uint32_t sb = smem_u32(smem);
    const int tid = threadIdx.x;
    const int warp = tid >> 5, lane = tid & 31;
    const int c0 = blockIdx.x * TN;

    float* a_sp = (float*)(smem + AS_OFF);
    int*   lblp = (int*)(smem + LBL_OFF);

    // labels + per-class scales
    const int is64 = g_lab64;
    for (int i = tid; i < B_ROWS; i += 256) lblp[i] = load_label(label, i, is64);
    if (tid < TN) {
        int cg = c0 + tid;
        a_sp[tid] = g_ascale[(cg < NCLS) ? cg : (NCLS - 1)];
    }

    // W tile + X block 0 via cp.async (24 x 16B chunks per 192-elem row)
    for (int i = tid; i < TN * 24; i += 256) {
        int c = i / 24, j = i % 24;
        int cg = c0 + c; if (cg >= NCLS) cg = NCLS - 1;  // clamp; epilogue guards
        CP_ASYNC16(sb + WS_OFF + c * STRB + j * 16,
                   (const char*)g_wbf + (size_t)cg * (DIM * 2) + j * 16);
    }
    for (int i = tid; i < RB * 24; i += 256) {
        int r = i / 24, j = i % 24;
        CP_ASYNC16(sb + XS0_OFF + r * STRB + j * 16,
                   (const char*)g_xbf + (size_t)r * (DIM * 2) + j * 16);
    }
    CP_COMMIT();
    CP_WAIT0();
    __syncthreads();

    // warp grid: 4 (rows) x 2 (cols); each warp: 16 rows x 64 cols
    const int wm = warp >> 1, wn = warp & 1;
    const int g = lane >> 2, tig = lane & 3;

    // ldmatrix lane address components
    const int a_row = wm * 16 + (lane & 7) + ((lane >> 3) & 1) * 8;
    const uint32_t a_koff = ((lane >> 4) & 1) * 16;  // bytes
    const int b_mat = lane >> 3;
    const int b_row = wn * 64 + (b_mat >> 1) * 8 + (lane & 7);
    const uint32_t b_koff = (b_mat & 1) * 16;  // bytes
    uint32_t b_addr[4];
    #pragma unroll
    for (int p = 0; p < 4; p++)
        b_addr[p] = sb + WS_OFF + (b_row + p * 16) * STRB + b_koff;

    for (int blk = 0; blk < NRB; blk++) {
        const uint32_t xbase = sb + ((blk & 1) ? XS1_OFF : XS0_OFF);
        if (blk + 1 < NRB) {  // prefetch next X block under compute
            uint32_t xb = sb + (((blk + 1) & 1) ? XS1_OFF : XS0_OFF);
            for (int i = tid; i < RB * 24; i += 256) {
                int r = i / 24, j = i % 24;
                CP_ASYNC16(xb + r * STRB + j * 16,
                           (const char*)g_xbf + ((size_t)(blk + 1) * RB + r) * (DIM * 2) + j * 16);
            }
            CP_COMMIT();
        }

        float acc[8][4];
        #pragma unroll
        for (int ni = 0; ni < 8; ni++)
            #pragma unroll
            for (int q = 0; q < 4; q++) acc[ni][q] = 0.f;

        const uint32_t xa0 = xbase + a_row * STRB + a_koff;

        #pragma unroll
        for (int kb = 0; kb < NKB; kb++) {
            const uint32_t kadd = kb * 32;  // 16 bf16 = 32 bytes
            uint32_t af[4];
            LDSM4(af[0], af[1], af[2], af[3], xa0 + kadd);
            uint32_t bf[8][2];
            #pragma unroll
            for (int p = 0; p < 4; p++)
                LDSM4(bf[2 * p][0], bf[2 * p][1], bf[2 * p + 1][0], bf[2 * p + 1][1],
                      b_addr[p] + kadd);
            #pragma unroll
            for (int ni = 0; ni < 8; ni++)
                mma_bf16(acc[ni], af, bf[ni]);
        }

        // fused epilogue: margin at label col, exp2 partial sum, argmax
        #pragma unroll
        for (int half = 0; half < 2; half++) {
            int row = blk * RB + wm * 16 + g + half * 8;
            int lab = lblp[row];
            float psum = 0.f, tmax = -1e30f;
            int cmax = 0;
            #pragma unroll
            for (int ni = 0; ni < 8; ni++) {
                #pragma unroll
                for (int q = 0; q < 2; q++) {
                    int ci = wn * 64 + ni * 8 + tig * 2 + q;
                    int c = c0 + ci;
                    if (c < NCLS) {
                        float t = acc[ni][half * 2 + q] * a_sp[ci];
                        if (c == lab) {
                            float cs = t * (1.0f / SLOG2E);
                            float sn = sqrtf(fmaxf(1.0f - cs * cs, 0.f));
                            float ph = cs * COS_M_C - sn * SIN_M_C;
                            if (!(cs - TH_C > 0.f)) ph = cs - MM_C;
                            t = ph * SLOG2E;
                            g_label_t[row] = t;  // unique writer per row
                        }
                        psum += exp2f(t);
                        if (t > tmax) { tmax = t; cmax = c; }
                    }
                }
            }
            psum += __shfl_xor_sync(0xffffffffu, psum, 1);
            psum += __shfl_xor_sync(0xffffffffu, psum, 2);
            unsigned long long key =
                ((unsigned long long)fkey(tmax) << 32) |
                (unsigned long long)(0xFFFFFFFFu - (unsigned)cmax);
            unsigned long long o;
            o = __shfl_xor_sync(0xffffffffu, key, 1); key = key > o ? key : o;
            o = __shfl_xor_sync(0xffffffffu, key, 2); key = key > o ? key : o;
            if (tig == 0) {
                atomicAdd(&g_rowsum[row], psum);
                atomicMax(&g_rowmax[row], key);
            }
        }

        if (blk + 1 < NRB) {
            CP_WAIT0();
            __syncthreads();
        }
    }
}

// ---------------- kernel 2: finalize loss + prec1 ----------------
__global__ void finalize_kernel(const void* __restrict__ label, float* __restrict__ out,
                                int out_n) {
    __shared__ float sl[B_ROWS];
    __shared__ int   sh[B_ROWS];
    int b = threadIdx.x;
    float s = g_rowsum[b];
    float loss_b = (log2f(s) - g_label_t[b]) * 0.6931471805599453f;
    unsigned int idx = 0xFFFFFFFFu - (unsigned int)(g_rowmax[b] & 0xFFFFFFFFull);
    int lab = load_label(label, b, g_lab64);
    sl[b] = loss_b;
    sh[b] = (idx == (unsigned int)lab) ? 1 : 0;
    __syncthreads();
    for (int st = B_ROWS / 2; st > 0; st >>= 1) {
        if (b < st) { sl[b] += sl[b + st]; sh[b] += sh[b + st]; }
        __syncthreads();
    }
    if (b == 0) {
        out[0] = sl[0] * (1.0f / B_ROWS);
        if (out_n > 1) out[1] = (float)sh[0] * (100.0f / B_ROWS);
    }
}

// ---------------- launch ----------------
extern "C" void kernel_launch(void* const* d_in, const int* in_sizes, int n_in,
                              void* d_out, int out_size) {
    const float* x   = (const float*)d_in[0];
    const float* wgt = (const float*)d_in[1];
    const void*  lab = d_in[2];
    float* out = (float*)d_out;
    (void)in_sizes; (void)n_in;

    cudaFuncSetAttribute(gemm_epi_kernel, cudaFuncAttributeMaxDynamicSharedMemorySize,
                         SMEM_TOTAL);

    detect_kernel<<<1, 1024>>>((const int*)lab);
    prep_x_kernel<<<B_ROWS, DIM>>>(x);
    prep_w_kernel<<<(NCLS + 3) / 4, 128>>>(wgt);
    gemm_epi_kernel<<<NT, 256, SMEM_TOTAL>>>(lab);
    finalize_kernel<<<1, B_ROWS>>>(lab, out, out_size);
}

// round 11
// speedup vs baseline: 2.3970x; 1.2527x over previous
#include <cuda_runtime.h>
#include <cuda_bf16.h>
#include <cstdint>

// ---------------- problem constants ----------------
#define B_ROWS 1024
#define DIM    192
#define NCLS   100000

#define TN  128                        // classes per CTA tile
#define RB  64                         // rows per inner block
#define NRB (B_ROWS / RB)              // 16
#define NT  ((NCLS + TN - 1) / TN)     // 782 tiles
#define NKB (DIM / 16)                 // 12 k16-steps
#define STR 200                        // smem row stride in bf16 elems (400B)
#define STRB (STR * 2)                 // 400 bytes

#define S_SCALE 30.0f
#define LOG2E_F 1.4426950408889634f
#define SLOG2E  (S_SCALE * LOG2E_F)
#define COS_M_C 0.98006657784124163f
#define SIN_M_C 0.19866933079506122f
#define TH_C    (-0.98006657784124163f)
#define MM_C    0.039733866159012244f

// ---------------- smem layout (bytes): exactly 76800 -> 3 CTAs/SM ----------------
#define WS_OFF   0                       // W tile: 128 rows x 400B = 51200
#define WS_SZ    (TN * STRB)
#define XS_OFF   (WS_OFF + WS_SZ)        // X block: 64 rows x 400B = 25600 (single buf)
#define XS_SZ    (RB * STRB)
#define SMEM_TOTAL (XS_OFF + XS_SZ)      // 76800

// ---------------- scratch (device globals; no allocation) ----------------
__device__ float              g_rowsum[B_ROWS];
__device__ unsigned long long g_rowmax[B_ROWS];
__device__ float              g_label_t[B_ROWS];
__device__ __nv_bfloat16      g_xbf[B_ROWS * DIM];        // normalized x, bf16
__device__ __nv_bfloat16      g_wbf[(size_t)NCLS * DIM];  // w rounded to bf16
__device__ float              g_ascale[NCLS];             // S*log2e / ||w_bf16||
__device__ int                g_lbl[B_ROWS];              // labels as int32
__device__ int                g_lab64;

// ---------------- helpers ----------------
__device__ __forceinline__ uint32_t smem_u32(const void* p) {
    uint32_t a;
    asm("{ .reg .u64 t; cvta.to.shared.u64 t, %1; cvt.u32.u64 %0, t; }" : "=r"(a) : "l"(p));
    return a;
}
#define CP_ASYNC16(dst, src) \
    asm volatile("cp.async.cg.shared.global [%0], [%1], 16;" :: "r"(dst), "l"(src) : "memory")
#define CP_COMMIT() asm volatile("cp.async.commit_group;" ::: "memory")
#define CP_WAIT0()  asm volatile("cp.async.wait_group 0;" ::: "memory")

#define LDSM4(r0, r1, r2, r3, a) \
    asm volatile("ldmatrix.sync.aligned.m8n8.x4.shared.b16 {%0,%1,%2,%3}, [%4];" \
                 : "=r"(r0), "=r"(r1), "=r"(r2), "=r"(r3) : "r"(a))

__device__ __forceinline__ void mma_bf16(float* d, const uint32_t* a, const uint32_t* b) {
    asm volatile(
        "mma.sync.aligned.m16n8k16.row.col.f32.bf16.bf16.f32 "
        "{%0,%1,%2,%3}, {%4,%5,%6,%7}, {%8,%9}, {%0,%1,%2,%3};"
        : "+f"(d[0]), "+f"(d[1]), "+f"(d[2]), "+f"(d[3])
        : "r"(a[0]), "r"(a[1]), "r"(a[2]), "r"(a[3]), "r"(b[0]), "r"(b[1]));
}
__device__ __forceinline__ unsigned int fkey(float v) {
    unsigned int u = __float_as_uint(v);
    return (u & 0x80000000u) ? ~u : (u | 0x80000000u);
}
__device__ __forceinline__ int load_label(const void* lp, int i, int is64) {
    if (is64) return (int)(((const long long*)lp)[i]);
    return ((const int*)lp)[i];
}

// ---------------- kernel 0a: detect label dtype ----------------
__global__ void detect_kernel(const int* __restrict__ lw) {
    __shared__ int any;
    if (threadIdx.x == 0) any = 0;
    __syncthreads();
    int i = threadIdx.x;
    if (i < 512 && lw[2 * i + 1] != 0) atomicOr(&any, 1);
    __syncthreads();
    if (threadIdx.x == 0) g_lab64 = (any == 0) ? 1 : 0;
}

// ---------------- kernel 0b: normalize x -> bf16, labels -> int32, zero scratch ---
__global__ void prep_x_kernel(const float* __restrict__ x, const void* __restrict__ label) {
    int b = blockIdx.x, k = threadIdx.x;  // 192 threads
    float v = x[b * DIM + k];
    float ss = v * v;
    #pragma unroll
    for (int o = 16; o > 0; o >>= 1) ss += __shfl_xor_sync(0xffffffffu, ss, o);
    __shared__ float wp[6];
    __shared__ float inv_s;
    if ((k & 31) == 0) wp[k >> 5] = ss;
    __syncthreads();
    if (k == 0) {
        float t = 0.f;
        #pragma unroll
        for (int i = 0; i < 6; i++) t += wp[i];
        inv_s = 1.0f / fmaxf(sqrtf(t), 1e-12f);
        g_rowsum[b] = 0.f;
        g_rowmax[b] = 0ull;
        g_lbl[b] = load_label(label, b, g_lab64);
    }
    __syncthreads();
    g_xbf[b * DIM + k] = __float2bfloat16(v * inv_s);
}

// ---------------- kernel 0c: w -> bf16 + per-class combined scale ----------------
__global__ void prep_w_kernel(const float* __restrict__ wgt) {
    int c = blockIdx.x * 4 + (threadIdx.x >> 5);  // 1 class per warp
    int l = threadIdx.x & 31;
    if (c >= NCLS) return;
    const float* wr = wgt + (size_t)c * DIM;
    __nv_bfloat16* wo = g_wbf + (size_t)c * DIM;
    float ss = 0.f;
    #pragma unroll
    for (int i = 0; i < 6; i++) {
        float v = wr[l * 6 + i];
        __nv_bfloat16 bv = __float2bfloat16(v);
        float vb = __bfloat162float(bv);
        ss += vb * vb;
        wo[l * 6 + i] = bv;
    }
    #pragma unroll
    for (int o = 16; o > 0; o >>= 1) ss += __shfl_xor_sync(0xffffffffu, ss, o);
    if (l == 0) g_ascale[c] = (ss > 0.f) ? SLOG2E * rsqrtf(ss) : 0.f;
}

// ---------------- kernel 1: bf16 HMMA GEMM + fused margin/softmax epilogue --------
__global__ void __launch_bounds__(256, 3)
gemm_epi_kernel() {
    extern __shared__ char smem[];
    const uint32_t sb = smem_u32(smem);
    const int tid = threadIdx.x;
    const int warp = tid >> 5, lane = tid & 31;
    const int c0 = blockIdx.x * TN;

    // W tile + X block 0 via cp.async (24 x 16B chunks per 192-elem row)
    for (int i = tid; i < TN * 24; i += 256) {
        int c = i / 24, j = i % 24;
        int cg = c0 + c; if (cg >= NCLS) cg = NCLS - 1;  // clamp; epilogue guards
        CP_ASYNC16(sb + WS_OFF + c * STRB + j * 16,
                   (const char*)g_wbf + (size_t)cg * (DIM * 2) + j * 16);
    }
    for (int i = tid; i < RB * 24; i += 256) {
        int r = i / 24, j = i % 24;
        CP_ASYNC16(sb + XS_OFF + r * STRB + j * 16,
                   (const char*)g_xbf + (size_t)r * (DIM * 2) + j * 16);
    }
    CP_COMMIT();

    // warp grid: 2 (rows) x 4 (cols); each warp: 32 rows x 32 cols
    const int wm = warp >> 2, wn = warp & 3;
    const int g = lane >> 2, tig = lane & 3;

    // per-thread class scales (block-invariant): 8 cols
    float asv[4][2];
    #pragma unroll
    for (int ni = 0; ni < 4; ni++)
        #pragma unroll
        for (int q = 0; q < 2; q++) {
            int c = c0 + wn * 32 + ni * 8 + tig * 2 + q;
            asv[ni][q] = __ldg(&g_ascale[(c < NCLS) ? c : (NCLS - 1)]);
        }

    // ldmatrix lane address components
    const int a_row = wm * 32 + (lane & 7) + ((lane >> 3) & 1) * 8;
    const uint32_t a_koff = ((lane >> 4) & 1) * 16;  // bytes
    const uint32_t xa0 = sb + XS_OFF + a_row * STRB + a_koff;
    const uint32_t xa1 = xa0 + 16 * STRB;

    const int b_mat = lane >> 3;
    const int b_row = wn * 32 + (b_mat >> 1) * 8 + (lane & 7);
    const uint32_t b_koff = (b_mat & 1) * 16;  // bytes
    uint32_t b_addr[2];
    #pragma unroll
    for (int p = 0; p < 2; p++)
        b_addr[p] = sb + WS_OFF + (b_row + p * 16) * STRB + b_koff;

    CP_WAIT0();
    __syncthreads();

    for (int blk = 0; blk < NRB; blk++) {
        float acc[2][4][4];
        #pragma unroll
        for (int mi = 0; mi < 2; mi++)
            #pragma unroll
            for (int ni = 0; ni < 4; ni++)
                #pragma unroll
                for (int q = 0; q < 4; q++) acc[mi][ni][q] = 0.f;

        #pragma unroll
        for (int kb = 0; kb < NKB; kb++) {
            const uint32_t kadd = kb * 32;  // 16 bf16 = 32 bytes
            uint32_t af[2][4];
            LDSM4(af[0][0], af[0][1], af[0][2], af[0][3], xa0 + kadd);
            LDSM4(af[1][0], af[1][1], af[1][2], af[1][3], xa1 + kadd);
            uint32_t bf[4][2];
            #pragma unroll
            for (int p = 0; p < 2; p++)
                LDSM4(bf[2 * p][0], bf[2 * p][1], bf[2 * p + 1][0], bf[2 * p + 1][1],
                      b_addr[p] + kadd);
            #pragma unroll
            for (int mi = 0; mi < 2; mi++)
                #pragma unroll
                for (int ni = 0; ni < 4; ni++)
                    mma_bf16(acc[mi][ni], af[mi], bf[ni]);
        }

        // all warps done reading X -> start next X load; epilogue overlaps it
        if (blk + 1 < NRB) {
            __syncthreads();
            for (int i = tid; i < RB * 24; i += 256) {
                int r = i / 24, j = i % 24;
                CP_ASYNC16(sb + XS_OFF + r * STRB + j * 16,
                           (const char*)g_xbf + ((size_t)(blk + 1) * RB + r) * (DIM * 2) + j * 16);
            }
            CP_COMMIT();
        }

        // fused epilogue: margin at label col, exp2 partial sum, argmax
        #pragma unroll
        for (int mi = 0; mi < 2; mi++) {
            #pragma unroll
            for (int half = 0; half < 2; half++) {
                int row = blk * RB + wm * 32 + mi * 16 + g + half * 8;
                int lab = __ldg(&g_lbl[row]);
                float psum = 0.f, tmax = -1e30f;
                int cmax = 0;
                #pragma unroll
                for (int ni = 0; ni < 4; ni++) {
                    #pragma unroll
                    for (int q = 0; q < 2; q++) {
                        int c = c0 + wn * 32 + ni * 8 + tig * 2 + q;
                        if (c < NCLS) {
                            float t = acc[mi][ni][half * 2 + q] * asv[ni][q];
                            if (c == lab) {
                                float cs = t * (1.0f / SLOG2E);
                                float sn = sqrtf(fmaxf(1.0f - cs * cs, 0.f));
                                float ph = cs * COS_M_C - sn * SIN_M_C;
                                if (!(cs - TH_C > 0.f)) ph = cs - MM_C;
                                t = ph * SLOG2E;
                                g_label_t[row] = t;  // unique writer per row
                            }
                            psum += exp2f(t);
                            if (t > tmax) { tmax = t; cmax = c; }
                        }
                    }
                }
                psum += __shfl_xor_sync(0xffffffffu, psum, 1);
                psum += __shfl_xor_sync(0xffffffffu, psum, 2);
                unsigned long long key =
                    ((unsigned long long)fkey(tmax) << 32) |
                    (unsigned long long)(0xFFFFFFFFu - (unsigned)cmax);
                unsigned long long o;
                o = __shfl_xor_sync(0xffffffffu, key, 1); key = key > o ? key : o;
                o = __shfl_xor_sync(0xffffffffu, key, 2); key = key > o ? key : o;
                if (tig == 0) {
                    atomicAdd(&g_rowsum[row], psum);
                    atomicMax(&g_rowmax[row], key);
                }
            }
        }

        if (blk + 1 < NRB) {
            CP_WAIT0();
            __syncthreads();
        }
    }
}

// ---------------- kernel 2: finalize loss + prec1 ----------------
__global__ void finalize_kernel(float* __restrict__ out, int out_n) {
    __shared__ float sl[B_ROWS];
    __shared__ int   sh[B_ROWS];
    int b = threadIdx.x;
    float s = g_rowsum[b];
    float loss_b = (log2f(s) - g_label_t[b]) * 0.6931471805599453f;
    unsigned int idx = 0xFFFFFFFFu - (unsigned int)(g_rowmax[b] & 0xFFFFFFFFull);
    int lab = g_lbl[b];
    sl[b] = loss_b;
    sh[b] = (idx == (unsigned int)lab) ? 1 : 0;
    __syncthreads();
    for (int st = B_ROWS / 2; st > 0; st >>= 1) {
        if (b < st) { sl[b] += sl[b + st]; sh[b] += sh[b + st]; }
        __syncthreads();
    }
    if (b == 0) {
        out[0] = sl[0] * (1.0f / B_ROWS);
        if (out_n > 1) out[1] = (float)sh[0] * (100.0f / B_ROWS);
    }
}

// ---------------- launch ----------------
extern "C" void kernel_launch(void* const* d_in, const int* in_sizes, int n_in,
                              void* d_out, int out_size) {
    const float* x   = (const float*)d_in[0];
    const float* wgt = (const float*)d_in[1];
    const void*  lab = d_in[2];
    float* out = (float*)d_out;
    (void)in_sizes; (void)n_in;

    cudaFuncSetAttribute(gemm_epi_kernel, cudaFuncAttributeMaxDynamicSharedMemorySize,
                         SMEM_TOTAL);
    cudaFuncSetAttribute(gemm_epi_kernel, cudaFuncAttributePreferredSharedMemoryCarveout,
                         100);

    detect_kernel<<<1, 1024>>>((const int*)lab);
    prep_x_kernel<<<B_ROWS, DIM>>>(x, lab);
    prep_w_kernel<<<(NCLS + 3) / 4, 128>>>(wgt);
    gemm_epi_kernel<<<NT, 256, SMEM_TOTAL>>>();
    finalize_kernel<<<1, B_ROWS>>>(out, out_size);
}

// round 12
// speedup vs baseline: 2.8174x; 1.1754x over previous
#include <cuda_runtime.h>
#include <cuda_bf16.h>
#include <cstdint>

// ---------------- problem constants ----------------
#define B_ROWS 1024
#define DIM    192
#define NCLS   100000

#define TN  128                        // classes per CTA tile
#define RB  64                         // rows per inner block
#define NRB (B_ROWS / RB)              // 16
#define NT  ((NCLS + TN - 1) / TN)     // 782 tiles
#define NOOR ((float)(NT * TN - NCLS)) // 96 out-of-range cols -> each row sum += 96*exp2(0)
#define NKB (DIM / 16)                 // 12 k16-steps
#define STR 200                        // smem row stride in bf16 elems (400B)
#define STRB (STR * 2)                 // 400 bytes

#define S_SCALE 30.0f
#define LOG2E_F 1.4426950408889634f
#define SLOG2E  (S_SCALE * LOG2E_F)
#define COS_M_C 0.98006657784124163f
#define SIN_M_C 0.19866933079506122f
#define TH_C    (-0.98006657784124163f)
#define MM_C    0.039733866159012244f

// ---------------- smem layout (bytes): exactly 76800 -> 3 CTAs/SM ----------------
#define WS_OFF   0                       // W tile: 128 rows x 400B = 51200
#define WS_SZ    (TN * STRB)
#define XS_OFF   (WS_OFF + WS_SZ)        // X block: 64 rows x 400B = 25600 (single buf)
#define XS_SZ    (RB * STRB)
#define SMEM_TOTAL (XS_OFF + XS_SZ)      // 76800

// ---------------- scratch (device globals; no allocation) ----------------
__device__ float              g_rowsum[B_ROWS];
__device__ unsigned long long g_rowmax[B_ROWS];
__device__ float              g_label_t[B_ROWS];
__device__ __nv_bfloat16      g_xbf[B_ROWS * DIM];        // normalized x, bf16
__device__ __nv_bfloat16      g_wbf[(size_t)NCLS * DIM];  // w rounded to bf16
__device__ float              g_ascale[NCLS];             // S*log2e / ||w_bf16||
__device__ int                g_lbl[B_ROWS];              // labels as int32
__device__ int                g_lab64;

// ---------------- helpers ----------------
__device__ __forceinline__ uint32_t smem_u32(const void* p) {
    uint32_t a;
    asm("{ .reg .u64 t; cvta.to.shared.u64 t, %1; cvt.u32.u64 %0, t; }" : "=r"(a) : "l"(p));
    return a;
}
__device__ __forceinline__ float ex2_fast(float x) {   // single MUFU.EX2
    float r;
    asm("ex2.approx.ftz.f32 %0, %1;" : "=f"(r) : "f"(x));
    return r;
}
__device__ __forceinline__ float sqrt_fast(float x) {
    float r;
    asm("sqrt.approx.ftz.f32 %0, %1;" : "=f"(r) : "f"(x));
    return r;
}
#define CP_ASYNC16(dst, src) \
    asm volatile("cp.async.cg.shared.global [%0], [%1], 16;" :: "r"(dst), "l"(src) : "memory")
#define CP_COMMIT() asm volatile("cp.async.commit_group;" ::: "memory")
#define CP_WAIT0()  asm volatile("cp.async.wait_group 0;" ::: "memory")

#define LDSM4(r0, r1, r2, r3, a) \
    asm volatile("ldmatrix.sync.aligned.m8n8.x4.shared.b16 {%0,%1,%2,%3}, [%4];" \
                 : "=r"(r0), "=r"(r1), "=r"(r2), "=r"(r3) : "r"(a))

__device__ __forceinline__ void mma_bf16(float* d, const uint32_t* a, const uint32_t* b) {
    asm volatile(
        "mma.sync.aligned.m16n8k16.row.col.f32.bf16.bf16.f32 "
        "{%0,%1,%2,%3}, {%4,%5,%6,%7}, {%8,%9}, {%0,%1,%2,%3};"
        : "+f"(d[0]), "+f"(d[1]), "+f"(d[2]), "+f"(d[3])
        : "r"(a[0]), "r"(a[1]), "r"(a[2]), "r"(a[3]), "r"(b[0]), "r"(b[1]));
}
__device__ __forceinline__ unsigned int fkey(float v) {
    unsigned int u = __float_as_uint(v);
    return (u & 0x80000000u) ? ~u : (u | 0x80000000u);
}
__device__ __forceinline__ int load_label(const void* lp, int i, int is64) {
    if (is64) return (int)(((const long long*)lp)[i]);
    return ((const int*)lp)[i];
}

// ---------------- kernel 0a: detect label dtype ----------------
__global__ void detect_kernel(const int* __restrict__ lw) {
    __shared__ int any;
    if (threadIdx.x == 0) any = 0;
    __syncthreads();
    int i = threadIdx.x;
    if (i < 512 && lw[2 * i + 1] != 0) atomicOr(&any, 1);
    __syncthreads();
    if (threadIdx.x == 0) g_lab64 = (any == 0) ? 1 : 0;
}

// ---------------- kernel 0b: normalize x -> bf16, labels -> int32, zero scratch ---
__global__ void prep_x_kernel(const float* __restrict__ x, const void* __restrict__ label) {
    int b = blockIdx.x, k = threadIdx.x;  // 192 threads
    float v = x[b * DIM + k];
    float ss = v * v;
    #pragma unroll
    for (int o = 16; o > 0; o >>= 1) ss += __shfl_xor_sync(0xffffffffu, ss, o);
    __shared__ float wp[6];
    __shared__ float inv_s;
    if ((k & 31) == 0) wp[k >> 5] = ss;
    __syncthreads();
    if (k == 0) {
        float t = 0.f;
        #pragma unroll
        for (int i = 0; i < 6; i++) t += wp[i];
        inv_s = 1.0f / fmaxf(sqrtf(t), 1e-12f);
        g_rowsum[b] = 0.f;
        g_rowmax[b] = 0ull;
        g_lbl[b] = load_label(label, b, g_lab64);
    }
    __syncthreads();
    g_xbf[b * DIM + k] = __float2bfloat16(v * inv_s);
}

// ---------------- kernel 0c: w -> bf16 + per-class combined scale ----------------
__global__ void prep_w_kernel(const float* __restrict__ wgt) {
    int c = blockIdx.x * 4 + (threadIdx.x >> 5);  // 1 class per warp
    int l = threadIdx.x & 31;
    if (c >= NCLS) return;
    const float* wr = wgt + (size_t)c * DIM;
    __nv_bfloat16* wo = g_wbf + (size_t)c * DIM;
    float ss = 0.f;
    #pragma unroll
    for (int i = 0; i < 6; i++) {
        float v = wr[l * 6 + i];
        __nv_bfloat16 bv = __float2bfloat16(v);
        float vb = __bfloat162float(bv);
        ss += vb * vb;
        wo[l * 6 + i] = bv;
    }
    #pragma unroll
    for (int o = 16; o > 0; o >>= 1) ss += __shfl_xor_sync(0xffffffffu, ss, o);
    if (l == 0) g_ascale[c] = (ss > 0.f) ? SLOG2E * rsqrtf(ss) : 0.f;
}

// ---------------- kernel 1: bf16 HMMA GEMM + fused margin/softmax epilogue --------
__global__ void __launch_bounds__(256, 3)
gemm_epi_kernel() {
    extern __shared__ char smem[];
    const uint32_t sb = smem_u32(smem);
    const int tid = threadIdx.x;
    const int warp = tid >> 5, lane = tid & 31;
    const int c0 = blockIdx.x * TN;

    // W tile + X block 0 via cp.async (24 x 16B chunks per 192-elem row)
    for (int i = tid; i < TN * 24; i += 256) {
        int c = i / 24, j = i % 24;
        int cg = c0 + c; if (cg >= NCLS) cg = NCLS - 1;  // clamp (asv=0 kills OOR cols)
        CP_ASYNC16(sb + WS_OFF + c * STRB + j * 16,
                   (const char*)g_wbf + (size_t)cg * (DIM * 2) + j * 16);
    }
    for (int i = tid; i < RB * 24; i += 256) {
        int r = i / 24, j = i % 24;
        CP_ASYNC16(sb + XS_OFF + r * STRB + j * 16,
                   (const char*)g_xbf + (size_t)r * (DIM * 2) + j * 16);
    }
    CP_COMMIT();

    // warp grid: 2 (rows) x 4 (cols); each warp: 32 rows x 32 cols
    const int wm = warp >> 2, wn = warp & 3;
    const int g = lane >> 2, tig = lane & 3;

    // per-thread class scales (block-invariant): 8 cols; OOR -> 0 so t=0, exp2=1
    // (each row sum gains exactly NOOR=96; finalize subtracts it)
    float asv[4][2];
    #pragma unroll
    for (int ni = 0; ni < 4; ni++)
        #pragma unroll
        for (int q = 0; q < 2; q++) {
            int c = c0 + wn * 32 + ni * 8 + tig * 2 + q;
            asv[ni][q] = (c < NCLS) ? __ldg(&g_ascale[c]) : 0.f;
        }

    // ldmatrix lane address components
    const int a_row = wm * 32 + (lane & 7) + ((lane >> 3) & 1) * 8;
    const uint32_t a_koff = ((lane >> 4) & 1) * 16;  // bytes
    const uint32_t xa0 = sb + XS_OFF + a_row * STRB + a_koff;
    const uint32_t xa1 = xa0 + 16 * STRB;

    const int b_mat = lane >> 3;
    const int b_row = wn * 32 + (b_mat >> 1) * 8 + (lane & 7);
    const uint32_t b_koff = (b_mat & 1) * 16;  // bytes
    uint32_t b_addr[2];
    #pragma unroll
    for (int p = 0; p < 2; p++)
        b_addr[p] = sb + WS_OFF + (b_row + p * 16) * STRB + b_koff;

    CP_WAIT0();
    __syncthreads();

    for (int blk = 0; blk < NRB; blk++) {
        float acc[2][4][4];
        #pragma unroll
        for (int mi = 0; mi < 2; mi++)
            #pragma unroll
            for (int ni = 0; ni < 4; ni++)
                #pragma unroll
                for (int q = 0; q < 4; q++) acc[mi][ni][q] = 0.f;

        #pragma unroll
        for (int kb = 0; kb < NKB; kb++) {
            const uint32_t kadd = kb * 32;  // 16 bf16 = 32 bytes
            uint32_t af[2][4];
            LDSM4(af[0][0], af[0][1], af[0][2], af[0][3], xa0 + kadd);
            LDSM4(af[1][0], af[1][1], af[1][2], af[1][3], xa1 + kadd);
            uint32_t bf[4][2];
            #pragma unroll
            for (int p = 0; p < 2; p++)
                LDSM4(bf[2 * p][0], bf[2 * p][1], bf[2 * p + 1][0], bf[2 * p + 1][1],
                      b_addr[p] + kadd);
            #pragma unroll
            for (int mi = 0; mi < 2; mi++)
                #pragma unroll
                for (int ni = 0; ni < 4; ni++)
                    mma_bf16(acc[mi][ni], af[mi], bf[ni]);
        }

        // all warps done reading X -> start next X load; epilogue overlaps it
        if (blk + 1 < NRB) {
            __syncthreads();
            for (int i = tid; i < RB * 24; i += 256) {
                int r = i / 24, j = i % 24;
                CP_ASYNC16(sb + XS_OFF + r * STRB + j * 16,
                           (const char*)g_xbf + ((size_t)(blk + 1) * RB + r) * (DIM * 2) + j * 16);
            }
            CP_COMMIT();
        }

        // fused epilogue: margin at label col, exp2 partial sum, argmax (no bounds check)
        #pragma unroll
        for (int mi = 0; mi < 2; mi++) {
            #pragma unroll
            for (int half = 0; half < 2; half++) {
                int row = blk * RB + wm * 32 + mi * 16 + g + half * 8;
                int lab = __ldg(&g_lbl[row]);
                float psum = 0.f, tmax = -1e30f;
                int cmax = 0;
                #pragma unroll
                for (int ni = 0; ni < 4; ni++) {
                    #pragma unroll
                    for (int q = 0; q < 2; q++) {
                        int c = c0 + wn * 32 + ni * 8 + tig * 2 + q;
                        float t = acc[mi][ni][half * 2 + q] * asv[ni][q];
                        if (c == lab) {
                            float cs = t * (1.0f / SLOG2E);
                            float sn = sqrt_fast(fmaxf(1.0f - cs * cs, 0.f));
                            float ph = cs * COS_M_C - sn * SIN_M_C;
                            if (!(cs - TH_C > 0.f)) ph = cs - MM_C;
                            t = ph * SLOG2E;
                            g_label_t[row] = t;  // unique writer per row
                        }
                        psum += ex2_fast(t);
                        if (t > tmax) { tmax = t; cmax = c; }
                    }
                }
                psum += __shfl_xor_sync(0xffffffffu, psum, 1);
                psum += __shfl_xor_sync(0xffffffffu, psum, 2);
                unsigned long long key =
                    ((unsigned long long)fkey(tmax) << 32) |
                    (unsigned long long)(0xFFFFFFFFu - (unsigned)cmax);
                unsigned long long o;
                o = __shfl_xor_sync(0xffffffffu, key, 1); key = key > o ? key : o;
                o = __shfl_xor_sync(0xffffffffu, key, 2); key = key > o ? key : o;
                if (tig == 0) {
                    atomicAdd(&g_rowsum[row], psum);
                    atomicMax(&g_rowmax[row], key);
                }
            }
        }

        if (blk + 1 < NRB) {
            CP_WAIT0();
            __syncthreads();
        }
    }
}

// ---------------- kernel 2: finalize loss + prec1 ----------------
__global__ void finalize_kernel(float* __restrict__ out, int out_n) {
    __shared__ float sl[B_ROWS];
    __shared__ int   sh[B_ROWS];
    int b = threadIdx.x;
    float s = g_rowsum[b] - NOOR;  // remove the 96 exp2(0)=1 dummy-column terms
    float loss_b = (log2f(s) - g_label_t[b]) * 0.6931471805599453f;
    unsigned int idx = 0xFFFFFFFFu - (unsigned int)(g_rowmax[b] & 0xFFFFFFFFull);
    int lab = g_lbl[b];
    sl[b] = loss_b;
    sh[b] = (idx == (unsigned int)lab) ? 1 : 0;
    __syncthreads();
    for (int st = B_ROWS / 2; st > 0; st >>= 1) {
        if (b < st) { sl[b] += sl[b + st]; sh[b] += sh[b + st]; }
        __syncthreads();
    }
    if (b == 0) {
        out[0] = sl[0] * (1.0f / B_ROWS);
        if (out_n > 1) out[1] = (float)sh[0] * (100.0f / B_ROWS);
    }
}

// ---------------- launch ----------------
extern "C" void kernel_launch(void* const* d_in, const int* in_sizes, int n_in,
                              void* d_out, int out_size) {
    const float* x   = (const float*)d_in[0];
    const float* wgt = (const float*)d_in[1];
    const void*  lab = d_in[2];
    float* out = (float*)d_out;
    (void)in_sizes; (void)n_in;

    cudaFuncSetAttribute(gemm_epi_kernel, cudaFuncAttributeMaxDynamicSharedMemorySize,
                         SMEM_TOTAL);
    cudaFuncSetAttribute(gemm_epi_kernel, cudaFuncAttributePreferredSharedMemoryCarveout,
                         100);

    detect_kernel<<<1, 1024>>>((const int*)lab);
    prep_x_kernel<<<B_ROWS, DIM>>>(x, lab);
    prep_w_kernel<<<(NCLS + 3) / 4, 128>>>(wgt);
    gemm_epi_kernel<<<NT, 256, SMEM_TOTAL>>>();
    finalize_kernel<<<1, B_ROWS>>>(out, out_size);
}